// round 13
// baseline (speedup 1.0000x reference)
#include <cuda_runtime.h>
#include <cuda_fp16.h>
#include <cstdint>

// ---------------- problem constants ----------------
#define BB    16
#define CIN   512
#define COUT  512
#define SDIM  512
#define HI    32
#define WI    32
#define HO    64
#define WO    64
#define PADW  66
#define KTOT  (9 * CIN)          // 4608

#define LIN_SCALE  0.04419417382415922f
#define CONV_SCALE 0.014731391274719742f
#define ACT_GAIN   1.4142135623730951f
#define NEG_SLOPE  0.2f
#define EPS_DEMOD  1e-8f

// ---------------- device scratch ----------------
__device__ float g_s[BB * CIN];
__device__ float g_demod[BB * COUT];
__device__ __align__(16) __half g_wt[(size_t)COUT * KTOT];            // fp16, word-pair-permuted
__device__ float g_wsq[COUT * CIN];
__device__ float g_xt[(size_t)BB * HI * WI * CIN];                    // channel-last input (fp32)
__device__ __align__(16) __half g_xm[(size_t)BB * PADW * PADW * CIN]; // fp16, permuted, padded upsample

// Word-pair permutation within each 16-half group: word w (0..7, w=k>>1)
// stored at position 2*(w&3) + (w>>2), so words (w, w+4) are adjacent.
// One LDS.64 then yields both k-halves of an m16n8k16 fragment (a0+a2 / b0+b1).
__device__ __forceinline__ int hperm(int i) {
    const int k = i & 15;
    const int w = k >> 1;
    const int p = ((w & 3) << 1) | (w >> 2);
    return (i & ~15) | (p << 1) | (k & 1);
}

// ---------------- helpers ----------------
__device__ __forceinline__ uint32_t smem_u32(const void* p) {
    uint32_t a;
    asm("{ .reg .u64 t; cvta.to.shared.u64 t, %1; cvt.u32.u64 %0, t; }"
        : "=r"(a) : "l"(p));
    return a;
}
__device__ __forceinline__ void cpasync16(uint32_t dst, const void* src) {
    asm volatile("cp.async.cg.shared.global [%0], [%1], 16;"
                 :: "r"(dst), "l"(src) : "memory");
}
__device__ __forceinline__ void cp_commit() {
    asm volatile("cp.async.commit_group;" ::: "memory");
}
template<int N> __device__ __forceinline__ void cp_wait() {
    asm volatile("cp.async.wait_group %0;" :: "n"(N) : "memory");
}
__device__ __forceinline__ void mma_f16(float* c, uint32_t a0, uint32_t a1,
                                        uint32_t a2, uint32_t a3,
                                        uint32_t b0, uint32_t b1) {
    asm volatile(
        "mma.sync.aligned.m16n8k16.row.col.f32.f16.f16.f32 "
        "{%0,%1,%2,%3}, {%4,%5,%6,%7}, {%8,%9}, {%0,%1,%2,%3};"
        : "+f"(c[0]), "+f"(c[1]), "+f"(c[2]), "+f"(c[3])
        : "r"(a0), "r"(a1), "r"(a2), "r"(a3), "r"(b0), "r"(b1));
}

// ---------------- kernel 1: style ----------------
__global__ void style_kernel(const float* __restrict__ w,
                             const float* __restrict__ lin_w,
                             const float* __restrict__ lin_b)
{
    const int b = blockIdx.x, i = threadIdx.x;
    __shared__ float ws[SDIM];
    ws[i] = w[b * SDIM + i];
    __syncthreads();
    const float* lw = lin_w + (size_t)i * SDIM;
    float acc = 0.f;
#pragma unroll 8
    for (int j = 0; j < SDIM; ++j) acc = fmaf(ws[j], lw[j], acc);
    g_s[b * CIN + i] = acc * LIN_SCALE + lin_b[i];
}

// ---------------- kernel 2: weight K-major (fp16, permuted) + sumsq --------
__global__ void wprep_kernel(const float* __restrict__ conv_w)
{
    const int o = blockIdx.x, i = threadIdx.x;
    const float* wp = conv_w + ((size_t)o * CIN + i) * 9;
    const int ip = hperm(i);
    float q = 0.f;
#pragma unroll
    for (int kk = 0; kk < 9; ++kk) {
        const float v = wp[kk] * CONV_SCALE;
        g_wt[(size_t)o * KTOT + kk * CIN + ip] = __float2half(v);
        q = fmaf(v, v, q);   // exact fp32 for demod
    }
    g_wsq[o * CIN + i] = q;
}

// ---------------- kernel 3: demod ----------------
__global__ void demod_kernel()
{
    const int b = blockIdx.x, o = threadIdx.x;
    __shared__ float s2[CIN];
    const float sv = g_s[b * CIN + o];
    s2[o] = sv * sv;
    __syncthreads();
    const float* wq = g_wsq + (size_t)o * CIN;
    float acc = 0.f;
#pragma unroll 8
    for (int i = 0; i < CIN; ++i) acc = fmaf(wq[i], s2[i], acc);
    g_demod[b * COUT + o] = rsqrtf(acc + EPS_DEMOD);
}

// ---------------- kernel 4a: transpose x to channel-last ----------------
__global__ void transpose_kernel(const float* __restrict__ x)
{
    __shared__ float tile[32][33];
    const int b = blockIdx.z, p0 = blockIdx.x * 32, c0 = blockIdx.y * 32;
    const int tx = threadIdx.x, ty = threadIdx.y;     // (32, 8)
    for (int i = ty; i < 32; i += 8)
        tile[i][tx] = x[((size_t)(b * CIN) + c0 + i) * (HI * WI) + p0 + tx];
    __syncthreads();
    for (int i = ty; i < 32; i += 8)
        g_xt[((size_t)(b * HI * WI) + p0 + i) * CIN + c0 + tx] = tile[tx][i];
}

// ------ kernel 4b: upsample*style, channel-last, zero halo, fp16, permuted -
__global__ void upmod_cl_kernel()
{
    const int r = blockIdx.x;         // 0..65
    const int b = blockIdx.y;
    const int ci = threadIdx.x;       // 512
    const int cip = hperm(ci);
    __half* dst = g_xm + ((size_t)(b * PADW + r) * PADW) * CIN + cip;
    const __half hz = __float2half(0.f);
    if (r == 0 || r == PADW - 1) {
        for (int c = 0; c < PADW; ++c) dst[(size_t)c * CIN] = hz;
        return;
    }
    const int oy = r - 1, my = oy >> 1;
    int iy0, iy1; float wy0;
    if (oy & 1) { iy0 = my; iy1 = min(my + 1, HI - 1); wy0 = 0.75f; }
    else        { iy0 = max(my - 1, 0); iy1 = my;      wy0 = 0.25f; }
    const float wy1 = 1.f - wy0;
    const float s = g_s[b * CIN + ci];
    const float* xb = g_xt + (size_t)b * HI * WI * CIN + ci;
    dst[0] = hz;
    dst[(size_t)(PADW - 1) * CIN] = hz;
    for (int c = 1; c < PADW - 1; ++c) {
        const int ox = c - 1, mx = ox >> 1;
        int ix0, ix1; float wx0;
        if (ox & 1) { ix0 = mx; ix1 = min(mx + 1, WI - 1); wx0 = 0.75f; }
        else        { ix0 = max(mx - 1, 0); ix1 = mx;      wx0 = 0.25f; }
        const float wx1 = 1.f - wx0;
        const float v00 = xb[(size_t)(iy0 * WI + ix0) * CIN];
        const float v01 = xb[(size_t)(iy0 * WI + ix1) * CIN];
        const float v10 = xb[(size_t)(iy1 * WI + ix0) * CIN];
        const float v11 = xb[(size_t)(iy1 * WI + ix1) * CIN];
        dst[(size_t)c * CIN] = __float2half(
            (wy0 * (wx0 * v00 + wx1 * v01) + wy1 * (wx0 * v10 + wx1 * v11)) * s);
    }
}

// ---------------- kernel 5: fp16 mma.sync conv + fused epilogue ------------
// CTA tile: M=128 x N=128 x K-chunk 32 halfs; 144 chunks.
// 4 warps 2x2, warp tile 64x64 (low bytes/MAC) at 128 threads/CTA, but now
// 3 CTAs/SM (12 warps/SM) via 16KB stages: K-chunk 32 + SEGMENT SWIZZLE
// (physical 16B segment = (seg + row) & 3) -> zero padding, conflict-free for
// cp.async stores and both LDS.64 fragment-gather patterns.
#define RSH 32                             // halfs per smem row (no pad)
#define A_HALFS (128 * RSH)                // 4096
#define B_HALFS (128 * RSH)                // 4096
#define STAGE_HALFS (A_HALFS + B_HALFS)    // 8192
#define STAGE_BYTES (STAGE_HALFS * 2)      // 16384
#define CONV_SMEM (2 * STAGE_BYTES)        // 32768
#define NCHUNK 144
#define CTHREADS 128

// physical half-offset of logical half 'h' (0..31) in row 'row'
__device__ __forceinline__ int sw_off(int row, int h) {
    return row * RSH + ((((h >> 3) + row) & 3) << 3) + (h & 7);
}

__global__ __launch_bounds__(CTHREADS, 3)
void conv_mma_kernel(const float* __restrict__ noise,
                     const float* __restrict__ nw_p,
                     float* __restrict__ out)
{
    extern __shared__ __half sm[];
    const uint32_t sbase = smem_u32(sm);

    const int t = threadIdx.x;
    const int wid = t >> 5, lane = t & 31;
    const int g = lane >> 2, tg = lane & 3;
    const int wm = wid & 1, wn = wid >> 1;   // 2 x 2 warps, warp tile 64x64

    const int cout0 = blockIdx.x * 128;
    const int py2   = blockIdx.y * 2;
    const int b     = blockIdx.z;

    const __half* xmb = g_xm + (size_t)b * PADW * PADW * CIN;
    const int f2i = t & 3;     // 16B (8-half) segment within 32-half k-chunk
    const int rowi = t >> 2;   // 0..31

    auto stage = [&](int it, int s) {
        const int tap = it >> 4;             // 16 chunks of 32 per tap
        const int ci0 = (it & 15) << 5;
        const int ky = tap / 3, kx = tap - 3 * ky;
        const uint32_t abase = sbase + s * STAGE_BYTES;
        const __half* wsrc = g_wt + (size_t)cout0 * KTOT + tap * CIN + ci0 + f2i * 8;
#pragma unroll
        for (int j = 0; j < 4; ++j) {
            const int row = rowi + 32 * j;
            cpasync16(abase + (uint32_t)sw_off(row, f2i * 8) * 2,
                      wsrc + (size_t)row * KTOT);
        }
        const uint32_t bbase = abase + A_HALFS * 2;
#pragma unroll
        for (int j = 0; j < 4; ++j) {
            const int n = rowi + 32 * j;
            const int r = py2 + (n >> 6) + ky;
            const int c = (n & 63) + kx;
            cpasync16(bbase + (uint32_t)sw_off(n, f2i * 8) * 2,
                      xmb + ((size_t)r * PADW + c) * CIN + ci0 + f2i * 8);
        }
        cp_commit();
    };

    float acc[4][8][4];
#pragma unroll
    for (int mt = 0; mt < 4; ++mt)
#pragma unroll
        for (int nt = 0; nt < 8; ++nt)
#pragma unroll
            for (int q = 0; q < 4; ++q) acc[mt][nt][q] = 0.f;

    stage(0, 0);

    for (int it = 0; it < NCHUNK; ++it) {
        cp_wait<0>();            // stage(it) fully arrived
        __syncthreads();         // all warps past compute(it-1); slot (it+1)&1 reusable
        if (it + 1 < NCHUNK) stage(it + 1, (it + 1) & 1);

        const __half* A = sm + (it & 1) * STAGE_HALFS;
        const __half* B = A + A_HALFS;

#pragma unroll
        for (int ks = 0; ks < 2; ++ks) {
            const int h = ks * 16 + 4 * tg;     // logical half offset (perm pairs)
            uint2 afr[4][2];                    // [mt][row g / row g+8] = (a0,a2)/(a1,a3)
#pragma unroll
            for (int mt = 0; mt < 4; ++mt) {
                const int mb = wm * 64 + mt * 16;
                afr[mt][0] = *(const uint2*)&A[sw_off(mb + g, h)];
                afr[mt][1] = *(const uint2*)&A[sw_off(mb + g + 8, h)];
            }
#pragma unroll
            for (int nt = 0; nt < 8; ++nt) {
                const int nb = wn * 64 + nt * 8;
                const uint2 bfr = *(const uint2*)&B[sw_off(nb + g, h)];  // (b0,b1)
#pragma unroll
                for (int mt = 0; mt < 4; ++mt)
                    mma_f16(acc[mt][nt],
                            afr[mt][0].x, afr[mt][1].x,
                            afr[mt][0].y, afr[mt][1].y,
                            bfr.x, bfr.y);
            }
        }
    }

    // fused epilogue: demod, noise, leaky relu, gain
    const float nwv = nw_p[0];
#pragma unroll
    for (int mt = 0; mt < 4; ++mt) {
        const int m0 = cout0 + wm * 64 + mt * 16 + g;
        const float dm0 = g_demod[b * COUT + m0];
        const float dm1 = g_demod[b * COUT + m0 + 8];
#pragma unroll
        for (int nt = 0; nt < 8; ++nt) {
            const int n = wn * 64 + nt * 8 + tg * 2;
            const int row = py2 + (n >> 6);
            const int col = n & 63;
            const float* nz = noise + ((size_t)b * HO + row) * WO + col;
            const float n0 = nwv * nz[0], n1 = nwv * nz[1];
            float* o0 = out + (((size_t)(b * COUT + m0)) * HO + row) * WO + col;
            float* o1 = o0 + (size_t)8 * HO * WO;
            float v;
            float2 r0, r1;
            v = acc[mt][nt][0] * dm0 + n0; r0.x = ((v >= 0.f) ? v : NEG_SLOPE * v) * ACT_GAIN;
            v = acc[mt][nt][1] * dm0 + n1; r0.y = ((v >= 0.f) ? v : NEG_SLOPE * v) * ACT_GAIN;
            v = acc[mt][nt][2] * dm1 + n0; r1.x = ((v >= 0.f) ? v : NEG_SLOPE * v) * ACT_GAIN;
            v = acc[mt][nt][3] * dm1 + n1; r1.y = ((v >= 0.f) ? v : NEG_SLOPE * v) * ACT_GAIN;
            *(float2*)o0 = r0;
            *(float2*)o1 = r1;
        }
    }
}

// ---------------- launch ----------------
extern "C" void kernel_launch(void* const* d_in, const int* in_sizes, int n_in,
                              void* d_out, int out_size)
{
    const float* x      = (const float*)d_in[0];
    const float* w      = (const float*)d_in[1];
    const float* noise  = (const float*)d_in[2];
    const float* lin_w  = (const float*)d_in[3];
    const float* lin_b  = (const float*)d_in[4];
    const float* conv_w = (const float*)d_in[5];
    const float* nw     = (const float*)d_in[6];
    float* out = (float*)d_out;

    cudaFuncSetAttribute(conv_mma_kernel,
                         cudaFuncAttributeMaxDynamicSharedMemorySize, CONV_SMEM);

    style_kernel<<<BB, SDIM>>>(w, lin_w, lin_b);
    wprep_kernel<<<COUT, CIN>>>(conv_w);
    demod_kernel<<<BB, COUT>>>();
    transpose_kernel<<<dim3(32, 16, 16), dim3(32, 8)>>>(x);
    upmod_cl_kernel<<<dim3(PADW, BB), CIN>>>();

    dim3 grid(COUT / 128, (HO * WO) / 128, BB);
    conv_mma_kernel<<<grid, CTHREADS, CONV_SMEM>>>(noise, nw, out);
}

// round 15
// speedup vs baseline: 1.1927x; 1.1927x over previous
#include <cuda_runtime.h>
#include <cuda_fp16.h>
#include <cstdint>

// ---------------- problem constants ----------------
#define BB    16
#define CIN   512
#define COUT  512
#define SDIM  512
#define HI    32
#define WI    32
#define HO    64
#define WO    64
#define PADW  66
#define KTOT  (9 * CIN)          // 4608

#define LIN_SCALE  0.04419417382415922f
#define CONV_SCALE 0.014731391274719742f
#define ACT_GAIN   1.4142135623730951f
#define NEG_SLOPE  0.2f
#define EPS_DEMOD  1e-8f

// ---------------- device scratch ----------------
__device__ float g_s[BB * CIN];
__device__ float g_demod[BB * COUT];
__device__ __align__(16) __half g_wt[(size_t)COUT * KTOT];            // fp16, word-pair-permuted
__device__ float g_wsq[COUT * CIN];
__device__ float g_xt[(size_t)BB * HI * WI * CIN];                    // channel-last input (fp32)
__device__ __align__(16) __half g_xm[(size_t)BB * PADW * PADW * CIN]; // fp16, permuted, padded upsample

// Word-pair permutation within each 16-half group: word w (0..7, w=k>>1)
// stored at position 2*(w&3) + (w>>2), so words (w, w+4) are adjacent.
// One LDS.64 then yields both k-halves of an m16n8k16 fragment (a0+a2 / b0+b1).
__device__ __forceinline__ int hperm(int i) {
    const int k = i & 15;
    const int w = k >> 1;
    const int p = ((w & 3) << 1) | (w >> 2);
    return (i & ~15) | (p << 1) | (k & 1);
}

// ---------------- helpers ----------------
__device__ __forceinline__ uint32_t smem_u32(const void* p) {
    uint32_t a;
    asm("{ .reg .u64 t; cvta.to.shared.u64 t, %1; cvt.u32.u64 %0, t; }"
        : "=r"(a) : "l"(p));
    return a;
}
__device__ __forceinline__ void cpasync16(uint32_t dst, const void* src) {
    asm volatile("cp.async.cg.shared.global [%0], [%1], 16;"
                 :: "r"(dst), "l"(src) : "memory");
}
__device__ __forceinline__ void cp_commit() {
    asm volatile("cp.async.commit_group;" ::: "memory");
}
template<int N> __device__ __forceinline__ void cp_wait() {
    asm volatile("cp.async.wait_group %0;" :: "n"(N) : "memory");
}
__device__ __forceinline__ void mma_f16(float* c, uint32_t a0, uint32_t a1,
                                        uint32_t a2, uint32_t a3,
                                        uint32_t b0, uint32_t b1) {
    asm volatile(
        "mma.sync.aligned.m16n8k16.row.col.f32.f16.f16.f32 "
        "{%0,%1,%2,%3}, {%4,%5,%6,%7}, {%8,%9}, {%0,%1,%2,%3};"
        : "+f"(c[0]), "+f"(c[1]), "+f"(c[2]), "+f"(c[3])
        : "r"(a0), "r"(a1), "r"(a2), "r"(a3), "r"(b0), "r"(b1));
}

// ---------------- kernel 1: style ----------------
__global__ void style_kernel(const float* __restrict__ w,
                             const float* __restrict__ lin_w,
                             const float* __restrict__ lin_b)
{
    const int b = blockIdx.x, i = threadIdx.x;
    __shared__ float ws[SDIM];
    ws[i] = w[b * SDIM + i];
    __syncthreads();
    const float* lw = lin_w + (size_t)i * SDIM;
    float acc = 0.f;
#pragma unroll 8
    for (int j = 0; j < SDIM; ++j) acc = fmaf(ws[j], lw[j], acc);
    g_s[b * CIN + i] = acc * LIN_SCALE + lin_b[i];
}

// ---------------- kernel 2: weight K-major (fp16, permuted) + sumsq --------
__global__ void wprep_kernel(const float* __restrict__ conv_w)
{
    const int o = blockIdx.x, i = threadIdx.x;
    const float* wp = conv_w + ((size_t)o * CIN + i) * 9;
    const int ip = hperm(i);
    float q = 0.f;
#pragma unroll
    for (int kk = 0; kk < 9; ++kk) {
        const float v = wp[kk] * CONV_SCALE;
        g_wt[(size_t)o * KTOT + kk * CIN + ip] = __float2half(v);
        q = fmaf(v, v, q);   // exact fp32 for demod
    }
    g_wsq[o * CIN + i] = q;
}

// ---------------- kernel 3: demod ----------------
__global__ void demod_kernel()
{
    const int b = blockIdx.x, o = threadIdx.x;
    __shared__ float s2[CIN];
    const float sv = g_s[b * CIN + o];
    s2[o] = sv * sv;
    __syncthreads();
    const float* wq = g_wsq + (size_t)o * CIN;
    float acc = 0.f;
#pragma unroll 8
    for (int i = 0; i < CIN; ++i) acc = fmaf(wq[i], s2[i], acc);
    g_demod[b * COUT + o] = rsqrtf(acc + EPS_DEMOD);
}

// ---------------- kernel 4a: transpose x to channel-last ----------------
__global__ void transpose_kernel(const float* __restrict__ x)
{
    __shared__ float tile[32][33];
    const int b = blockIdx.z, p0 = blockIdx.x * 32, c0 = blockIdx.y * 32;
    const int tx = threadIdx.x, ty = threadIdx.y;     // (32, 8)
    for (int i = ty; i < 32; i += 8)
        tile[i][tx] = x[((size_t)(b * CIN) + c0 + i) * (HI * WI) + p0 + tx];
    __syncthreads();
    for (int i = ty; i < 32; i += 8)
        g_xt[((size_t)(b * HI * WI) + p0 + i) * CIN + c0 + tx] = tile[tx][i];
}

// ------ kernel 4b: upsample*style, channel-last, zero halo, fp16, permuted -
__global__ void upmod_cl_kernel()
{
    const int r = blockIdx.x;         // 0..65
    const int b = blockIdx.y;
    const int ci = threadIdx.x;       // 512
    const int cip = hperm(ci);
    __half* dst = g_xm + ((size_t)(b * PADW + r) * PADW) * CIN + cip;
    const __half hz = __float2half(0.f);
    if (r == 0 || r == PADW - 1) {
        for (int c = 0; c < PADW; ++c) dst[(size_t)c * CIN] = hz;
        return;
    }
    const int oy = r - 1, my = oy >> 1;
    int iy0, iy1; float wy0;
    if (oy & 1) { iy0 = my; iy1 = min(my + 1, HI - 1); wy0 = 0.75f; }
    else        { iy0 = max(my - 1, 0); iy1 = my;      wy0 = 0.25f; }
    const float wy1 = 1.f - wy0;
    const float s = g_s[b * CIN + ci];
    const float* xb = g_xt + (size_t)b * HI * WI * CIN + ci;
    dst[0] = hz;
    dst[(size_t)(PADW - 1) * CIN] = hz;
    for (int c = 1; c < PADW - 1; ++c) {
        const int ox = c - 1, mx = ox >> 1;
        int ix0, ix1; float wx0;
        if (ox & 1) { ix0 = mx; ix1 = min(mx + 1, WI - 1); wx0 = 0.75f; }
        else        { ix0 = max(mx - 1, 0); ix1 = mx;      wx0 = 0.25f; }
        const float wx1 = 1.f - wx0;
        const float v00 = xb[(size_t)(iy0 * WI + ix0) * CIN];
        const float v01 = xb[(size_t)(iy0 * WI + ix1) * CIN];
        const float v10 = xb[(size_t)(iy1 * WI + ix0) * CIN];
        const float v11 = xb[(size_t)(iy1 * WI + ix1) * CIN];
        dst[(size_t)c * CIN] = __float2half(
            (wy0 * (wx0 * v00 + wx1 * v01) + wy1 * (wx0 * v10 + wx1 * v11)) * s);
    }
}

// ---------------- kernel 5: fp16 mma.sync conv + fused epilogue ------------
// L2-traffic-minimized: per ci-chunk (64 ci), a 4-row x 66-col input WINDOW is
// loaded into smem ONCE and all 9 taps compute from it (tap = row/col offset
// in the window; col shifts move in 128B steps so alignment holds). B traffic
// drops 9x. Compute geometry = R11 (best): 8 warps 2x4, warp 64x32, chunk 64,
// one barrier per tap, RS=80 conflict-free, 2 CTAs/SM (83.2KB smem).
#define RS 80                              // halfs per smem row
#define A_HALFS (128 * RS)                 // 10240
#define WIN_ROWS (4 * PADW)                // 264
#define WIN_HALFS (WIN_ROWS * RS)          // 21120
#define CONV_SMEM ((2 * A_HALFS + WIN_HALFS) * 2)   // 83200 bytes
#define CTHREADS 256

__global__ __launch_bounds__(CTHREADS, 2)
void conv_mma_kernel(const float* __restrict__ noise,
                     const float* __restrict__ nw_p,
                     float* __restrict__ out)
{
    extern __shared__ __half sm[];
    const uint32_t sbase = smem_u32(sm);

    const int t = threadIdx.x;
    const int wid = t >> 5, lane = t & 31;
    const int g = lane >> 2, tg = lane & 3;
    const int wm = wid & 1, wn = wid >> 1;   // 2 x 4 warps, warp tile 64x32

    const int cout0 = blockIdx.x * 128;
    const int py2   = blockIdx.y * 2;
    const int b     = blockIdx.z;

    const __half* xmb = g_xm + (size_t)b * PADW * PADW * CIN;
    const int f4i = t & 7;     // 16B (8-half) segment within 64-half chunk
    const int row0 = t >> 3;   // 0..31

    // stage A tile for (cc, tap) into buffer s
    auto stageA = [&](int cc, int tap, int s) {
        const uint32_t abase = sbase + (uint32_t)s * A_HALFS * 2;
        const __half* wsrc = g_wt + (size_t)cout0 * KTOT + tap * CIN + cc * 64 + f4i * 8;
#pragma unroll
        for (int j = 0; j < 4; ++j) {
            const int row = row0 + 32 * j;
            cpasync16(abase + (uint32_t)(row * RS + f4i * 8) * 2,
                      wsrc + (size_t)row * KTOT);
        }
    };

    // load 4-row x 66-col x 64-ci window for ci-chunk cc
    auto loadWin = [&](int cc) {
        const uint32_t wbase = sbase + (uint32_t)(2 * A_HALFS) * 2;
        for (int idx = t; idx < WIN_ROWS * 8; idx += CTHREADS) {
            const int R = idx >> 3, seg = idx & 7;
            const int wr = R / PADW, c = R - wr * PADW;
            cpasync16(wbase + (uint32_t)(R * RS + seg * 8) * 2,
                      xmb + ((size_t)(py2 + wr) * PADW + c) * CIN + cc * 64 + seg * 8);
        }
    };

    float acc[4][4][4];
#pragma unroll
    for (int mt = 0; mt < 4; ++mt)
#pragma unroll
        for (int nt = 0; nt < 4; ++nt)
#pragma unroll
            for (int q = 0; q < 4; ++q) acc[mt][nt][q] = 0.f;

    loadWin(0);
    stageA(0, 0, 0);
    cp_commit();
    int buf = 0;

    for (int cc = 0; cc < 8; ++cc) {
        for (int tap = 0; tap < 9; ++tap) {
            cp_wait<0>();
            __syncthreads();
            if (tap < 8) { stageA(cc, tap + 1, buf ^ 1); cp_commit(); }

            const __half* A = sm + buf * A_HALFS;
            const __half* W = sm + 2 * A_HALFS;
            const int ky = tap / 3, kx = tap - 3 * ky;
            const int woff = ky * PADW + kx;

            // window row index per B fragment (independent of ks)
            int Rn[4];
#pragma unroll
            for (int nt = 0; nt < 4; ++nt) {
                const int n = wn * 32 + nt * 8 + g;
                Rn[nt] = ((n >> 6) * PADW + (n & 63) + woff) * RS;
            }

#pragma unroll
            for (int ks = 0; ks < 4; ++ks) {
                const int off = ks * 16 + 4 * tg;   // permuted word pair (tg, tg+4)
                uint2 afr[4][2];
#pragma unroll
                for (int mt = 0; mt < 4; ++mt) {
                    const int mb = wm * 64 + mt * 16;
                    afr[mt][0] = *(const uint2*)&A[(mb + g) * RS + off];
                    afr[mt][1] = *(const uint2*)&A[(mb + g + 8) * RS + off];
                }
#pragma unroll
                for (int nt = 0; nt < 4; ++nt) {
                    const uint2 bfr = *(const uint2*)&W[Rn[nt] + off];
#pragma unroll
                    for (int mt = 0; mt < 4; ++mt)
                        mma_f16(acc[mt][nt],
                                afr[mt][0].x, afr[mt][1].x,
                                afr[mt][0].y, afr[mt][1].y,
                                bfr.x, bfr.y);
                }
            }

            if (tap == 8 && cc < 7) {
                __syncthreads();            // window cc fully consumed
                loadWin(cc + 1);
                stageA(cc + 1, 0, buf ^ 1);
                cp_commit();
            }
            buf ^= 1;
        }
    }

    // fused epilogue: demod, noise, leaky relu, gain
    const float nwv = nw_p[0];
#pragma unroll
    for (int mt = 0; mt < 4; ++mt) {
        const int m0 = cout0 + wm * 64 + mt * 16 + g;
        const float dm0 = g_demod[b * COUT + m0];
        const float dm1 = g_demod[b * COUT + m0 + 8];
#pragma unroll
        for (int nt = 0; nt < 4; ++nt) {
            const int n = wn * 32 + nt * 8 + tg * 2;
            const int row = py2 + (n >> 6);
            const int col = n & 63;
            const float* nz = noise + ((size_t)b * HO + row) * WO + col;
            const float n0 = nwv * nz[0], n1 = nwv * nz[1];
            float* o0 = out + (((size_t)(b * COUT + m0)) * HO + row) * WO + col;
            float* o1 = o0 + (size_t)8 * HO * WO;
            float v;
            float2 r0, r1;
            v = acc[mt][nt][0] * dm0 + n0; r0.x = ((v >= 0.f) ? v : NEG_SLOPE * v) * ACT_GAIN;
            v = acc[mt][nt][1] * dm0 + n1; r0.y = ((v >= 0.f) ? v : NEG_SLOPE * v) * ACT_GAIN;
            v = acc[mt][nt][2] * dm1 + n0; r1.x = ((v >= 0.f) ? v : NEG_SLOPE * v) * ACT_GAIN;
            v = acc[mt][nt][3] * dm1 + n1; r1.y = ((v >= 0.f) ? v : NEG_SLOPE * v) * ACT_GAIN;
            *(float2*)o0 = r0;
            *(float2*)o1 = r1;
        }
    }
}

// ---------------- launch ----------------
extern "C" void kernel_launch(void* const* d_in, const int* in_sizes, int n_in,
                              void* d_out, int out_size)
{
    const float* x      = (const float*)d_in[0];
    const float* w      = (const float*)d_in[1];
    const float* noise  = (const float*)d_in[2];
    const float* lin_w  = (const float*)d_in[3];
    const float* lin_b  = (const float*)d_in[4];
    const float* conv_w = (const float*)d_in[5];
    const float* nw     = (const float*)d_in[6];
    float* out = (float*)d_out;

    cudaFuncSetAttribute(conv_mma_kernel,
                         cudaFuncAttributeMaxDynamicSharedMemorySize, CONV_SMEM);

    style_kernel<<<BB, SDIM>>>(w, lin_w, lin_b);
    wprep_kernel<<<COUT, CIN>>>(conv_w);
    demod_kernel<<<BB, COUT>>>();
    transpose_kernel<<<dim3(32, 16, 16), dim3(32, 8)>>>(x);
    upmod_cl_kernel<<<dim3(PADW, BB), CIN>>>();

    dim3 grid(COUT / 128, (HO * WO) / 128, BB);
    conv_mma_kernel<<<grid, CTHREADS, CONV_SMEM>>>(noise, nw, out);
}